// round 1
// baseline (speedup 1.0000x reference)
#include <cuda_runtime.h>
#include <math.h>

// ---------------- problem constants ----------------
#define NN     30000      // nodes
#define EMAX   480000     // edges (before self loops)
#define DIN    128
#define F1     256        // H1*DH
#define F2     64         // H2*DH
#define H1H    8
#define H2H    2
#define DHH    32
#define GG     64
#define DOUT   10
#define ETOT   (EMAX + NN)

// ---------------- scratch (device globals; no allocation allowed) ----------------
__device__ float g_xl1[NN * F1];
__device__ float g_xr1[NN * F1];
__device__ float g_h1 [NN * F1];
__device__ float g_xl2[NN * F2];
__device__ float g_xr2[NN * F2];
__device__ float g_h2 [NN * F2];
__device__ int   g_deg[NN + 1];
__device__ int   g_row[NN + 1];
__device__ int   g_cur[NN];
__device__ int   g_csr[ETOT];
__device__ float g_pool[GG * F2];

// ---------------- CSR build ----------------
__global__ void k_init_deg(int n) {
    int i = blockIdx.x * blockDim.x + threadIdx.x;
    if (i < n) g_deg[i] = 1;   // self loop
}

__global__ void k_hist(const int* __restrict__ ei, int E) {
    int e = blockIdx.x * blockDim.x + threadIdx.x;
    if (e < E) atomicAdd(&g_deg[ei[E + e]], 1);
}

// single-block exclusive scan over n elements (n = 30000)
__global__ void k_scan(int n) {
    __shared__ int sm[1024];
    __shared__ int carry;
    int tid = threadIdx.x;
    if (tid == 0) carry = 0;
    __syncthreads();
    for (int base = 0; base < n; base += 1024) {
        int i = base + tid;
        int v = (i < n) ? g_deg[i] : 0;
        sm[tid] = v;
        __syncthreads();
        for (int off = 1; off < 1024; off <<= 1) {
            int t = (tid >= off) ? sm[tid - off] : 0;
            __syncthreads();
            sm[tid] += t;
            __syncthreads();
        }
        int incl = sm[tid];
        if (i < n) g_row[i] = carry + incl - v;   // exclusive
        __syncthreads();
        if (tid == 0) carry += sm[1023];
        __syncthreads();
    }
    if (tid == 0) g_row[n] = carry;
}

__global__ void k_csr_init(int n) {
    int i = blockIdx.x * blockDim.x + threadIdx.x;
    if (i < n) {
        int r = g_row[i];
        g_csr[r] = i;          // self loop first
        g_cur[i] = r + 1;
    }
}

__global__ void k_scatter(const int* __restrict__ ei, int E) {
    int e = blockIdx.x * blockDim.x + threadIdx.x;
    if (e < E) {
        int dst = ei[E + e];
        int pos = atomicAdd(&g_cur[dst], 1);
        g_csr[pos] = ei[e];
    }
}

// ---------------- SGEMM: C[M,N] = A[M,K] @ B[K,N] (row-major) ----------------
// BM=128, BN=64, BK=16, 256 threads, 8x4 microtile
__global__ void k_sgemm(const float* __restrict__ A, const float* __restrict__ B,
                        float* __restrict__ C, int M, int K, int Nn) {
    __shared__ float Asm[16][128];   // transposed A tile
    __shared__ float Bsm[16][64];
    int tid = threadIdx.x;
    int bm = blockIdx.y * 128;
    int bn = blockIdx.x * 64;
    int tx = tid & 15;      // 0..15 -> cols tx*4
    int ty = tid >> 4;      // 0..15 -> rows ty*8

    float acc[8][4];
#pragma unroll
    for (int i = 0; i < 8; i++)
#pragma unroll
        for (int j = 0; j < 4; j++) acc[i][j] = 0.f;

    int la_r = tid >> 2;            // 0..63  (row within tile, +64 for second)
    int la_c = (tid & 3) * 4;       // k-col
    int lb_r = tid >> 4;            // 0..15
    int lb_c = (tid & 15) * 4;

    for (int k0 = 0; k0 < K; k0 += 16) {
        // load A tile (128x16) transposed
#pragma unroll
        for (int rep = 0; rep < 2; rep++) {
            int r = la_r + rep * 64;
            int gr = bm + r;
            float4 v = make_float4(0.f, 0.f, 0.f, 0.f);
            if (gr < M) v = *(const float4*)(A + (size_t)gr * K + k0 + la_c);
            Asm[la_c + 0][r] = v.x;
            Asm[la_c + 1][r] = v.y;
            Asm[la_c + 2][r] = v.z;
            Asm[la_c + 3][r] = v.w;
        }
        // load B tile (16x64)
        {
            float4 v = *(const float4*)(B + (size_t)(k0 + lb_r) * Nn + bn + lb_c);
            *(float4*)&Bsm[lb_r][lb_c] = v;
        }
        __syncthreads();
#pragma unroll
        for (int kk = 0; kk < 16; kk++) {
            float4 a0 = *(float4*)&Asm[kk][ty * 8];
            float4 a1 = *(float4*)&Asm[kk][ty * 8 + 4];
            float4 b0 = *(float4*)&Bsm[kk][tx * 4];
            float av[8] = {a0.x, a0.y, a0.z, a0.w, a1.x, a1.y, a1.z, a1.w};
            float bv[4] = {b0.x, b0.y, b0.z, b0.w};
#pragma unroll
            for (int i = 0; i < 8; i++)
#pragma unroll
                for (int j = 0; j < 4; j++)
                    acc[i][j] = fmaf(av[i], bv[j], acc[i][j]);
        }
        __syncthreads();
    }
#pragma unroll
    for (int i = 0; i < 8; i++) {
        int r = bm + ty * 8 + i;
        if (r < M) {
            float4 v = make_float4(acc[i][0], acc[i][1], acc[i][2], acc[i][3]);
            *(float4*)(C + (size_t)r * Nn + bn + tx * 4) = v;
        }
    }
}

// ---------------- GATv2 aggregation, layer 1 (H1=8 heads, dh=32, F=256) ----------------
// one warp per destination node; lane -> head = lane>>2, dims = (lane&3)*8 .. +8
__global__ void k_agg1(const float* __restrict__ att, const float* __restrict__ bias) {
    int warp = (blockIdx.x * blockDim.x + threadIdx.x) >> 5;
    if (warp >= NN) return;
    int lane = threadIdx.x & 31;
    int base = (lane >> 2) * 32 + (lane & 3) * 8;   // h*32 + sub*8

    float xr[8], av[8];
    {
        float4 r0 = *(const float4*)(g_xr1 + (size_t)warp * F1 + base);
        float4 r1 = *(const float4*)(g_xr1 + (size_t)warp * F1 + base + 4);
        xr[0]=r0.x; xr[1]=r0.y; xr[2]=r0.z; xr[3]=r0.w;
        xr[4]=r1.x; xr[5]=r1.y; xr[6]=r1.z; xr[7]=r1.w;
        float4 a0 = *(const float4*)(att + base);
        float4 a1 = *(const float4*)(att + base + 4);
        av[0]=a0.x; av[1]=a0.y; av[2]=a0.z; av[3]=a0.w;
        av[4]=a1.x; av[5]=a1.y; av[6]=a1.z; av[7]=a1.w;
    }

    float acc[8];
#pragma unroll
    for (int j = 0; j < 8; j++) acc[j] = 0.f;
    float m = -3.0e38f, z = 0.f;

    int e0 = g_row[warp], e1 = g_row[warp + 1];
    for (int e = e0; e < e1; e++) {
        int src = g_csr[e];
        const float* xp = g_xl1 + (size_t)src * F1 + base;
        float4 x0 = *(const float4*)xp;
        float4 x1 = *(const float4*)(xp + 4);
        float xj[8] = {x0.x, x0.y, x0.z, x0.w, x1.x, x1.y, x1.z, x1.w};
        float t = 0.f;
#pragma unroll
        for (int j = 0; j < 8; j++) {
            float v = xj[j] + xr[j];
            v = (v > 0.f) ? v : 0.2f * v;
            t = fmaf(v, av[j], t);
        }
        t += __shfl_xor_sync(0xffffffffu, t, 1);
        t += __shfl_xor_sync(0xffffffffu, t, 2);
        float mn = fmaxf(m, t);
        float sc = __expf(m - mn);
        float w  = __expf(t - mn);
        z = z * sc + w;
#pragma unroll
        for (int j = 0; j < 8; j++)
            acc[j] = fmaf(acc[j], sc, w * xj[j]);
        m = mn;
    }
    float inv = 1.f / z;
    float* out = g_h1 + (size_t)warp * F1 + base;
#pragma unroll
    for (int j = 0; j < 8; j++) {
        float v = acc[j] * inv + bias[base + j];
        out[j] = (v > 0.f) ? v : expm1f(v);        // ELU fused
    }
}

// ---------------- GATv2 aggregation, layer 2 (H2=2 heads, dh=32, F=64) ----------------
// one warp per node; lane -> head = lane>>4, dims = (lane&15)*2 .. +2
__global__ void k_agg2(const float* __restrict__ att, const float* __restrict__ bias) {
    int warp = (blockIdx.x * blockDim.x + threadIdx.x) >> 5;
    if (warp >= NN) return;
    int lane = threadIdx.x & 31;
    int base = (lane >> 4) * 32 + (lane & 15) * 2;

    float2 xr = *(const float2*)(g_xr2 + (size_t)warp * F2 + base);
    float2 av = *(const float2*)(att + base);

    float acc0 = 0.f, acc1 = 0.f;
    float m = -3.0e38f, z = 0.f;

    int e0 = g_row[warp], e1 = g_row[warp + 1];
    for (int e = e0; e < e1; e++) {
        int src = g_csr[e];
        float2 xj = *(const float2*)(g_xl2 + (size_t)src * F2 + base);
        float v0 = xj.x + xr.x; v0 = (v0 > 0.f) ? v0 : 0.2f * v0;
        float v1 = xj.y + xr.y; v1 = (v1 > 0.f) ? v1 : 0.2f * v1;
        float t = fmaf(v0, av.x, v1 * av.y);
        t += __shfl_xor_sync(0xffffffffu, t, 1);
        t += __shfl_xor_sync(0xffffffffu, t, 2);
        t += __shfl_xor_sync(0xffffffffu, t, 4);
        t += __shfl_xor_sync(0xffffffffu, t, 8);
        float mn = fmaxf(m, t);
        float sc = __expf(m - mn);
        float w  = __expf(t - mn);
        z = z * sc + w;
        acc0 = fmaf(acc0, sc, w * xj.x);
        acc1 = fmaf(acc1, sc, w * xj.y);
        m = mn;
    }
    float inv = 1.f / z;
    g_h2[(size_t)warp * F2 + base + 0] = acc0 * inv + bias[base + 0];
    g_h2[(size_t)warp * F2 + base + 1] = acc1 * inv + bias[base + 1];
}

// ---------------- mean pool over sorted batch (no atomics) ----------------
__device__ __forceinline__ int lb(const int* b, int n, int g) {
    int lo = 0, hi = n;
    while (lo < hi) { int mid = (lo + hi) >> 1; if (b[mid] < g) lo = mid + 1; else hi = mid; }
    return lo;
}

__global__ void k_pool(const int* __restrict__ batch, int n) {
    int g = blockIdx.x;           // 64 blocks x 64 threads
    int d = threadIdx.x;
    int s = lb(batch, n, g);
    int e = lb(batch, n, g + 1);
    float sum = 0.f;
    for (int i = s; i < e; i++) sum += g_h2[(size_t)i * F2 + d];
    int cnt = e - s; if (cnt < 1) cnt = 1;
    g_pool[g * F2 + d] = sum / (float)cnt;
}

// ---------------- MLP head: fc1(64->32) relu, fc2(32->16) relu, fc(16->10) ----------------
// out layout: c [64*10] then x2 [64*16]
__global__ void k_mlp(const float* __restrict__ fc1w, const float* __restrict__ fc1b,
                      const float* __restrict__ fc2w, const float* __restrict__ fc2b,
                      const float* __restrict__ fcw,  const float* __restrict__ fcb,
                      float* __restrict__ out) {
    __shared__ float hg[GG * 64];
    __shared__ float x1[GG * 32];
    __shared__ float x2[GG * 16];
    int tid = threadIdx.x;
    for (int i = tid; i < GG * 64; i += 256) hg[i] = g_pool[i];
    __syncthreads();
    for (int i = tid; i < GG * 32; i += 256) {
        int g = i >> 5, o = i & 31;
        float s = fc1b[o];
        for (int k = 0; k < 64; k++) s = fmaf(hg[g * 64 + k], fc1w[k * 32 + o], s);
        x1[i] = fmaxf(s, 0.f);
    }
    __syncthreads();
    for (int i = tid; i < GG * 16; i += 256) {
        int g = i >> 4, o = i & 15;
        float s = fc2b[o];
        for (int k = 0; k < 32; k++) s = fmaf(x1[g * 32 + k], fc2w[k * 16 + o], s);
        float v = fmaxf(s, 0.f);
        x2[i] = v;
        out[GG * DOUT + i] = v;
    }
    __syncthreads();
    for (int i = tid; i < GG * DOUT; i += 256) {
        int g = i / DOUT, o = i - g * DOUT;
        float s = fcb[o];
        for (int k = 0; k < 16; k++) s = fmaf(x2[g * 16 + k], fcw[k * DOUT + o], s);
        out[i] = s;
    }
}

// ---------------- launch ----------------
extern "C" void kernel_launch(void* const* d_in, const int* in_sizes, int n_in,
                              void* d_out, int out_size) {
    const float* x    = (const float*)d_in[0];
    const int*   ei   = (const int*)  d_in[1];
    const int*   bat  = (const int*)  d_in[2];
    const float* W1l  = (const float*)d_in[3];
    const float* W1r  = (const float*)d_in[4];
    const float* a1   = (const float*)d_in[5];
    const float* b1   = (const float*)d_in[6];
    const float* W2l  = (const float*)d_in[7];
    const float* W2r  = (const float*)d_in[8];
    const float* a2   = (const float*)d_in[9];
    const float* b2   = (const float*)d_in[10];
    const float* fc1w = (const float*)d_in[11];
    const float* fc1b = (const float*)d_in[12];
    const float* fc2w = (const float*)d_in[13];
    const float* fc2b = (const float*)d_in[14];
    const float* fcw  = (const float*)d_in[15];
    const float* fcb  = (const float*)d_in[16];
    float* out = (float*)d_out;

    int E = in_sizes[1] / 2;

    float *xl1, *xr1, *h1, *xl2, *xr2;
    cudaGetSymbolAddress((void**)&xl1, g_xl1);
    cudaGetSymbolAddress((void**)&xr1, g_xr1);
    cudaGetSymbolAddress((void**)&h1,  g_h1);
    cudaGetSymbolAddress((void**)&xl2, g_xl2);
    cudaGetSymbolAddress((void**)&xr2, g_xr2);

    // CSR build
    k_init_deg<<<(NN + 255) / 256, 256>>>(NN);
    k_hist<<<(E + 255) / 256, 256>>>(ei, E);
    k_scan<<<1, 1024>>>(NN);
    k_csr_init<<<(NN + 255) / 256, 256>>>(NN);
    k_scatter<<<(E + 255) / 256, 256>>>(ei, E);

    // layer 1 linear transforms
    {
        dim3 grid(F1 / 64, (NN + 127) / 128);
        k_sgemm<<<grid, 256>>>(x, W1l, xl1, NN, DIN, F1);
        k_sgemm<<<grid, 256>>>(x, W1r, xr1, NN, DIN, F1);
    }
    // layer 1 attention + aggregation (+ELU fused)
    k_agg1<<<(NN * 32 + 255) / 256, 256>>>(a1, b1);

    // layer 2 linear transforms
    {
        dim3 grid(F2 / 64, (NN + 127) / 128);
        k_sgemm<<<grid, 256>>>(h1, W2l, xl2, NN, F1, F2);
        k_sgemm<<<grid, 256>>>(h1, W2r, xr2, NN, F1, F2);
    }
    // layer 2 attention + aggregation (+bias)
    k_agg2<<<(NN * 32 + 255) / 256, 256>>>(a2, b2);

    // pool + MLP head
    k_pool<<<GG, 64>>>(bat, NN);
    k_mlp<<<1, 256>>>(fc1w, fc1b, fc2w, fc2b, fcw, fcb, out);
}

// round 3
// speedup vs baseline: 1.2810x; 1.2810x over previous
#include <cuda_runtime.h>
#include <math.h>
#include <stdint.h>

// ---------------- problem constants ----------------
#define NN     30000      // nodes
#define EMAX   480000     // edges (before self loops)
#define DIN    128
#define F1     256        // H1*DH
#define F2     64         // H2*DH
#define GG     64
#define DOUT   10
#define ETOT   (EMAX + NN)

// ---------------- scratch (device globals; no allocation allowed) ----------------
__device__ float g_xl1[NN * F1];
__device__ float g_xr1[NN * F1];
__device__ float g_h1 [NN * F1];
__device__ float g_xl2[NN * F2];
__device__ float g_xr2[NN * F2];
__device__ float g_h2 [NN * F2];
__device__ int   g_deg[NN + 1];
__device__ int   g_row[NN + 1];
__device__ int   g_cur[NN];
__device__ int   g_csr[ETOT];
__device__ float g_pool[GG * F2];
__device__ float g_w1lt[F1 * DIN];   // transposed weights [N, K]
__device__ float g_w1rt[F1 * DIN];
__device__ float g_w2lt[F2 * F1];
__device__ float g_w2rt[F2 * F1];

// ---------------- tf32 mma.sync helpers (arch-agnostic PTX; works on sm_103) ----
__device__ __forceinline__ uint32_t f2tf32(float f) {
    uint32_t u;
    asm("cvt.rna.tf32.f32 %0, %1;" : "=r"(u) : "f"(f));
    return u;
}

__device__ __forceinline__ void mma_m16n8k8(float* d, const uint32_t* a, const uint32_t* b) {
    asm("mma.sync.aligned.m16n8k8.row.col.f32.tf32.tf32.f32 "
        "{%0,%1,%2,%3},{%4,%5,%6,%7},{%8,%9},{%0,%1,%2,%3};"
        : "+f"(d[0]), "+f"(d[1]), "+f"(d[2]), "+f"(d[3])
        : "r"(a[0]), "r"(a[1]), "r"(a[2]), "r"(a[3]), "r"(b[0]), "r"(b[1]));
}

// ---------------- tf32 tensor GEMM: C[M,N] = A[M,K] @ Bt[N,K]^T ----------------
// 256 thr, BM=128, BN=64, BK=32; warps 4x2; warp tile 32x32 (2x4 m16n8 frags)
#define BKG 32
__global__ void __launch_bounds__(256) k_mma_gemm(const float* __restrict__ A,
                                                  const float* __restrict__ Bt,
                                                  float* __restrict__ C,
                                                  int M, int K, int Nn) {
    __shared__ uint32_t As[128][BKG + 4];
    __shared__ uint32_t Bs[64][BKG + 4];

    int tid  = threadIdx.x;
    int wid  = tid >> 5, lane = tid & 31;
    int g    = lane >> 2, t = lane & 3;
    int wm   = wid >> 1, wn = wid & 1;          // warp grid 4x2
    int wr   = wm * 32;                          // warp row in tile
    int wc   = wn * 32;                          // warp col in tile
    int m0   = blockIdx.y * 128;
    int n0   = blockIdx.x * 64;

    float acc[2][4][4];
#pragma unroll
    for (int i = 0; i < 2; i++)
#pragma unroll
        for (int j = 0; j < 4; j++)
#pragma unroll
            for (int q = 0; q < 4; q++) acc[i][j][q] = 0.f;

    int arow = tid >> 3;           // 0..31 (per pass of 32 rows)
    int ac4  = tid & 7;            // float4 col

    for (int k0 = 0; k0 < K; k0 += BKG) {
        // A tile: 128 x 32, convert to tf32 bits
#pragma unroll
        for (int p = 0; p < 4; p++) {
            int r = p * 32 + arow;
            int gr = m0 + r; if (gr >= M) gr = M - 1;
            float4 v = *(const float4*)(A + (size_t)gr * K + k0 + ac4 * 4);
            uint4 u = make_uint4(f2tf32(v.x), f2tf32(v.y), f2tf32(v.z), f2tf32(v.w));
            *(uint4*)&As[r][ac4 * 4] = u;
        }
        // B tile: 64 x 32 (Bt is [N,K], K contiguous)
#pragma unroll
        for (int p = 0; p < 2; p++) {
            int r = p * 32 + arow;
            float4 v = *(const float4*)(Bt + (size_t)(n0 + r) * K + k0 + ac4 * 4);
            uint4 u = make_uint4(f2tf32(v.x), f2tf32(v.y), f2tf32(v.z), f2tf32(v.w));
            *(uint4*)&Bs[r][ac4 * 4] = u;
        }
        __syncthreads();

#pragma unroll
        for (int ks = 0; ks < BKG / 8; ks++) {
            int kk = ks * 8;
            uint32_t af[2][4], bf[4][2];
#pragma unroll
            for (int mt = 0; mt < 2; mt++) {
                int r = wr + mt * 16 + g;
                af[mt][0] = As[r][kk + t];
                af[mt][1] = As[r + 8][kk + t];
                af[mt][2] = As[r][kk + t + 4];
                af[mt][3] = As[r + 8][kk + t + 4];
            }
#pragma unroll
            for (int nt = 0; nt < 4; nt++) {
                int n = wc + nt * 8 + g;
                bf[nt][0] = Bs[n][kk + t];
                bf[nt][1] = Bs[n][kk + t + 4];
            }
#pragma unroll
            for (int mt = 0; mt < 2; mt++)
#pragma unroll
                for (int nt = 0; nt < 4; nt++)
                    mma_m16n8k8(acc[mt][nt], af[mt], bf[nt]);
        }
        __syncthreads();
    }

    // epilogue
#pragma unroll
    for (int mt = 0; mt < 2; mt++) {
        int r0 = m0 + wr + mt * 16 + g;
        int r1 = r0 + 8;
#pragma unroll
        for (int nt = 0; nt < 4; nt++) {
            int cc = n0 + wc + nt * 8 + t * 2;
            if (r0 < M)
                *(float2*)(C + (size_t)r0 * Nn + cc) = make_float2(acc[mt][nt][0], acc[mt][nt][1]);
            if (r1 < M)
                *(float2*)(C + (size_t)r1 * Nn + cc) = make_float2(acc[mt][nt][2], acc[mt][nt][3]);
        }
    }
}

// ---------------- weight transpose: dst[n*R + r] = src[r*Cc + n] ----------------
__global__ void k_transpose(const float* __restrict__ src, float* __restrict__ dst,
                            int R, int Cc) {
    __shared__ float t[32][33];
    int c0 = blockIdx.x * 32, r0 = blockIdx.y * 32;
    int x = threadIdx.x, y = threadIdx.y;
    for (int i = y; i < 32; i += 8)
        if (r0 + i < R && c0 + x < Cc) t[i][x] = src[(size_t)(r0 + i) * Cc + c0 + x];
    __syncthreads();
    for (int i = y; i < 32; i += 8)
        if (c0 + i < Cc && r0 + x < R) dst[(size_t)(c0 + i) * R + r0 + x] = t[x][i];
}

// ---------------- CSR build ----------------
__global__ void k_init_deg(int n) {
    int i = blockIdx.x * blockDim.x + threadIdx.x;
    if (i < n) g_deg[i] = 1;   // self loop
}

__global__ void k_hist(const int* __restrict__ ei, int E) {
    int e = blockIdx.x * blockDim.x + threadIdx.x;
    if (e < E) atomicAdd(&g_deg[ei[E + e]], 1);
}

__global__ void k_scan(int n) {
    __shared__ int sm[1024];
    __shared__ int carry;
    int tid = threadIdx.x;
    if (tid == 0) carry = 0;
    __syncthreads();
    for (int base = 0; base < n; base += 1024) {
        int i = base + tid;
        int v = (i < n) ? g_deg[i] : 0;
        sm[tid] = v;
        __syncthreads();
        for (int off = 1; off < 1024; off <<= 1) {
            int t = (tid >= off) ? sm[tid - off] : 0;
            __syncthreads();
            sm[tid] += t;
            __syncthreads();
        }
        int incl = sm[tid];
        if (i < n) g_row[i] = carry + incl - v;
        __syncthreads();
        if (tid == 0) carry += sm[1023];
        __syncthreads();
    }
    if (tid == 0) g_row[n] = carry;
}

__global__ void k_csr_init(int n) {
    int i = blockIdx.x * blockDim.x + threadIdx.x;
    if (i < n) {
        int r = g_row[i];
        g_csr[r] = i;
        g_cur[i] = r + 1;
    }
}

__global__ void k_scatter(const int* __restrict__ ei, int E) {
    int e = blockIdx.x * blockDim.x + threadIdx.x;
    if (e < E) {
        int dst = ei[E + e];
        int pos = atomicAdd(&g_cur[dst], 1);
        g_csr[pos] = ei[e];
    }
}

// ---------------- GATv2 aggregation, layer 1 ----------------
__global__ void k_agg1(const float* __restrict__ att, const float* __restrict__ bias) {
    int warp = (blockIdx.x * blockDim.x + threadIdx.x) >> 5;
    if (warp >= NN) return;
    int lane = threadIdx.x & 31;
    int base = (lane >> 2) * 32 + (lane & 3) * 8;

    float xr[8], av[8];
    {
        float4 r0 = *(const float4*)(g_xr1 + (size_t)warp * F1 + base);
        float4 r1 = *(const float4*)(g_xr1 + (size_t)warp * F1 + base + 4);
        xr[0]=r0.x; xr[1]=r0.y; xr[2]=r0.z; xr[3]=r0.w;
        xr[4]=r1.x; xr[5]=r1.y; xr[6]=r1.z; xr[7]=r1.w;
        float4 a0 = *(const float4*)(att + base);
        float4 a1 = *(const float4*)(att + base + 4);
        av[0]=a0.x; av[1]=a0.y; av[2]=a0.z; av[3]=a0.w;
        av[4]=a1.x; av[5]=a1.y; av[6]=a1.z; av[7]=a1.w;
    }

    float acc[8];
#pragma unroll
    for (int j = 0; j < 8; j++) acc[j] = 0.f;
    float m = -3.0e38f, z = 0.f;

    int e0 = g_row[warp], e1 = g_row[warp + 1];
    for (int e = e0; e < e1; e++) {
        int src = g_csr[e];
        const float* xp = g_xl1 + (size_t)src * F1 + base;
        float4 x0 = *(const float4*)xp;
        float4 x1 = *(const float4*)(xp + 4);
        float xj[8] = {x0.x, x0.y, x0.z, x0.w, x1.x, x1.y, x1.z, x1.w};
        float t = 0.f;
#pragma unroll
        for (int j = 0; j < 8; j++) {
            float v = xj[j] + xr[j];
            v = (v > 0.f) ? v : 0.2f * v;
            t = fmaf(v, av[j], t);
        }
        t += __shfl_xor_sync(0xffffffffu, t, 1);
        t += __shfl_xor_sync(0xffffffffu, t, 2);
        float mn = fmaxf(m, t);
        float sc = __expf(m - mn);
        float w  = __expf(t - mn);
        z = z * sc + w;
#pragma unroll
        for (int j = 0; j < 8; j++)
            acc[j] = fmaf(acc[j], sc, w * xj[j]);
        m = mn;
    }
    float inv = 1.f / z;
    float* out = g_h1 + (size_t)warp * F1 + base;
#pragma unroll
    for (int j = 0; j < 8; j++) {
        float v = acc[j] * inv + bias[base + j];
        out[j] = (v > 0.f) ? v : expm1f(v);        // ELU fused
    }
}

// ---------------- GATv2 aggregation, layer 2 ----------------
__global__ void k_agg2(const float* __restrict__ att, const float* __restrict__ bias) {
    int warp = (blockIdx.x * blockDim.x + threadIdx.x) >> 5;
    if (warp >= NN) return;
    int lane = threadIdx.x & 31;
    int base = (lane >> 4) * 32 + (lane & 15) * 2;

    float2 xr = *(const float2*)(g_xr2 + (size_t)warp * F2 + base);
    float2 av = *(const float2*)(att + base);

    float acc0 = 0.f, acc1 = 0.f;
    float m = -3.0e38f, z = 0.f;

    int e0 = g_row[warp], e1 = g_row[warp + 1];
    for (int e = e0; e < e1; e++) {
        int src = g_csr[e];
        float2 xj = *(const float2*)(g_xl2 + (size_t)src * F2 + base);
        float v0 = xj.x + xr.x; v0 = (v0 > 0.f) ? v0 : 0.2f * v0;
        float v1 = xj.y + xr.y; v1 = (v1 > 0.f) ? v1 : 0.2f * v1;
        float t = fmaf(v0, av.x, v1 * av.y);
        t += __shfl_xor_sync(0xffffffffu, t, 1);
        t += __shfl_xor_sync(0xffffffffu, t, 2);
        t += __shfl_xor_sync(0xffffffffu, t, 4);
        t += __shfl_xor_sync(0xffffffffu, t, 8);
        float mn = fmaxf(m, t);
        float sc = __expf(m - mn);
        float w  = __expf(t - mn);
        z = z * sc + w;
        acc0 = fmaf(acc0, sc, w * xj.x);
        acc1 = fmaf(acc1, sc, w * xj.y);
        m = mn;
    }
    float inv = 1.f / z;
    g_h2[(size_t)warp * F2 + base + 0] = acc0 * inv + bias[base + 0];
    g_h2[(size_t)warp * F2 + base + 1] = acc1 * inv + bias[base + 1];
}

// ---------------- mean pool over sorted batch ----------------
__device__ __forceinline__ int lb(const int* b, int n, int g) {
    int lo = 0, hi = n;
    while (lo < hi) { int mid = (lo + hi) >> 1; if (b[mid] < g) lo = mid + 1; else hi = mid; }
    return lo;
}

__global__ void k_pool(const int* __restrict__ batch, int n) {
    int g = blockIdx.x;
    int d = threadIdx.x;
    int s = lb(batch, n, g);
    int e = lb(batch, n, g + 1);
    float sum = 0.f;
    for (int i = s; i < e; i++) sum += g_h2[(size_t)i * F2 + d];
    int cnt = e - s; if (cnt < 1) cnt = 1;
    g_pool[g * F2 + d] = sum / (float)cnt;
}

// ---------------- MLP head ----------------
__global__ void k_mlp(const float* __restrict__ fc1w, const float* __restrict__ fc1b,
                      const float* __restrict__ fc2w, const float* __restrict__ fc2b,
                      const float* __restrict__ fcw,  const float* __restrict__ fcb,
                      float* __restrict__ out) {
    __shared__ float hg[GG * 64];
    __shared__ float x1[GG * 32];
    __shared__ float x2[GG * 16];
    int tid = threadIdx.x;
    for (int i = tid; i < GG * 64; i += 256) hg[i] = g_pool[i];
    __syncthreads();
    for (int i = tid; i < GG * 32; i += 256) {
        int g = i >> 5, o = i & 31;
        float s = fc1b[o];
        for (int k = 0; k < 64; k++) s = fmaf(hg[g * 64 + k], fc1w[k * 32 + o], s);
        x1[i] = fmaxf(s, 0.f);
    }
    __syncthreads();
    for (int i = tid; i < GG * 16; i += 256) {
        int g = i >> 4, o = i & 15;
        float s = fc2b[o];
        for (int k = 0; k < 32; k++) s = fmaf(x1[g * 32 + k], fc2w[k * 16 + o], s);
        float v = fmaxf(s, 0.f);
        x2[i] = v;
        out[GG * DOUT + i] = v;
    }
    __syncthreads();
    for (int i = tid; i < GG * DOUT; i += 256) {
        int g = i / DOUT, o = i - g * DOUT;
        float s = fcb[o];
        for (int k = 0; k < 16; k++) s = fmaf(x2[g * 16 + k], fcw[k * DOUT + o], s);
        out[i] = s;
    }
}

// ---------------- launch ----------------
extern "C" void kernel_launch(void* const* d_in, const int* in_sizes, int n_in,
                              void* d_out, int out_size) {
    const float* x    = (const float*)d_in[0];
    const int*   ei   = (const int*)  d_in[1];
    const int*   bat  = (const int*)  d_in[2];
    const float* W1l  = (const float*)d_in[3];
    const float* W1r  = (const float*)d_in[4];
    const float* a1   = (const float*)d_in[5];
    const float* b1   = (const float*)d_in[6];
    const float* W2l  = (const float*)d_in[7];
    const float* W2r  = (const float*)d_in[8];
    const float* a2   = (const float*)d_in[9];
    const float* b2   = (const float*)d_in[10];
    const float* fc1w = (const float*)d_in[11];
    const float* fc1b = (const float*)d_in[12];
    const float* fc2w = (const float*)d_in[13];
    const float* fc2b = (const float*)d_in[14];
    const float* fcw  = (const float*)d_in[15];
    const float* fcb  = (const float*)d_in[16];
    float* out = (float*)d_out;

    int E = in_sizes[1] / 2;

    float *xl1, *xr1, *h1, *xl2, *xr2, *w1lt, *w1rt, *w2lt, *w2rt;
    cudaGetSymbolAddress((void**)&xl1, g_xl1);
    cudaGetSymbolAddress((void**)&xr1, g_xr1);
    cudaGetSymbolAddress((void**)&h1,  g_h1);
    cudaGetSymbolAddress((void**)&xl2, g_xl2);
    cudaGetSymbolAddress((void**)&xr2, g_xr2);
    cudaGetSymbolAddress((void**)&w1lt, g_w1lt);
    cudaGetSymbolAddress((void**)&w1rt, g_w1rt);
    cudaGetSymbolAddress((void**)&w2lt, g_w2lt);
    cudaGetSymbolAddress((void**)&w2rt, g_w2rt);

    // weight transposes first (GEMM is launch #6 so ncu -s 5 profiles it)
    k_transpose<<<dim3(F1 / 32, DIN / 32), dim3(32, 8)>>>(W1l, w1lt, DIN, F1);
    k_transpose<<<dim3(F1 / 32, DIN / 32), dim3(32, 8)>>>(W1r, w1rt, DIN, F1);
    k_transpose<<<dim3(F2 / 32, F1 / 32), dim3(32, 8)>>>(W2l, w2lt, F1, F2);
    k_transpose<<<dim3(F2 / 32, F1 / 32), dim3(32, 8)>>>(W2r, w2rt, F1, F2);
    k_init_deg<<<(NN + 255) / 256, 256>>>(NN);

    const int GRID_M = (NN + 127) / 128;   // 235
    // layer 1 linear transforms (tf32 tensor cores via mma.sync)
    k_mma_gemm<<<dim3(F1 / 64, GRID_M), 256>>>(x, w1lt, xl1, NN, DIN, F1);
    k_mma_gemm<<<dim3(F1 / 64, GRID_M), 256>>>(x, w1rt, xr1, NN, DIN, F1);

    // CSR build (independent of GEMMs)
    k_hist<<<(E + 255) / 256, 256>>>(ei, E);
    k_scan<<<1, 1024>>>(NN);
    k_csr_init<<<(NN + 255) / 256, 256>>>(NN);
    k_scatter<<<(E + 255) / 256, 256>>>(ei, E);

    // layer 1 attention + aggregation (+ELU fused)
    k_agg1<<<(NN * 32 + 255) / 256, 256>>>(a1, b1);

    // layer 2 linear transforms
    k_mma_gemm<<<dim3(F2 / 64, GRID_M), 256>>>(h1, w2lt, xl2, NN, F1, F2);
    k_mma_gemm<<<dim3(F2 / 64, GRID_M), 256>>>(h1, w2rt, xr2, NN, F1, F2);

    // layer 2 attention + aggregation (+bias)
    k_agg2<<<(NN * 32 + 255) / 256, 256>>>(a2, b2);

    // pool + MLP head
    k_pool<<<GG, 64>>>(bat, NN);
    k_mlp<<<1, 256>>>(fc1w, fc1b, fc2w, fc2b, fcw, fcb, out);
}

// round 4
// speedup vs baseline: 1.5225x; 1.1885x over previous
#include <cuda_runtime.h>
#include <math.h>
#include <stdint.h>

// ---------------- problem constants ----------------
#define NN     30000      // nodes
#define EMAX   480000     // edges (before self loops)
#define DIN    128
#define F1     256        // H1*DH
#define F2     64         // H2*DH
#define GG     64
#define DOUT   10
#define ETOT   (EMAX + NN)

// ---------------- scratch (device globals; no allocation allowed) ----------------
__device__ float g_xl1[NN * F1];
__device__ float g_xr1[NN * F1];
__device__ float g_h1 [NN * F1];
__device__ float g_xl2[NN * F2];
__device__ float g_xr2[NN * F2];
__device__ float g_h2 [NN * F2];
__device__ int   g_deg[NN + 1];
__device__ int   g_row[NN + 1];
__device__ int   g_cur[NN];
__device__ int   g_csr[ETOT];
__device__ float g_pool[GG * F2];

// ---------------- tf32 mma.sync helpers (arch-agnostic PTX; works on sm_103) ----
__device__ __forceinline__ uint32_t f2tf32(float f) {
    uint32_t u;
    asm("cvt.rna.tf32.f32 %0, %1;" : "=r"(u) : "f"(f));
    return u;
}

__device__ __forceinline__ void mma_m16n8k8(float* d, const uint32_t* a, const uint32_t* b) {
    asm("mma.sync.aligned.m16n8k8.row.col.f32.tf32.tf32.f32 "
        "{%0,%1,%2,%3},{%4,%5,%6,%7},{%8,%9},{%0,%1,%2,%3};"
        : "+f"(d[0]), "+f"(d[1]), "+f"(d[2]), "+f"(d[3])
        : "r"(a[0]), "r"(a[1]), "r"(a[2]), "r"(a[3]), "r"(b[0]), "r"(b[1]));
}

// ---------------- tf32 tensor GEMM (dual-B): C[M,N] = A[M,K] @ B[K,N] ---------
// 256 thr, BM=128, BN=64, BK=32; warps 4x2; warp tile 32x32 (2x4 m16n8 frags)
// B is consumed in natural [K,N] layout (transposed into SMEM at load time).
// grid.x = 2*(Nn/64): first half computes B0->C0, second half B1->C1.
#define BKG 32
__global__ void __launch_bounds__(256) k_mma_gemm2(const float* __restrict__ A,
                                                   const float* __restrict__ B0,
                                                   const float* __restrict__ B1,
                                                   float* __restrict__ C0,
                                                   float* __restrict__ C1,
                                                   int M, int K, int Nn) {
    __shared__ uint32_t As[128][BKG + 4];   // (4r+k) mod 32 -> conflict-free frags
    __shared__ uint32_t Bs[64][BKG + 5];    // (5n+k) mod 32 -> conflict-free stores

    int bx = blockIdx.x;
    int nblk = gridDim.x >> 1;
    const float* B = B0;
    float* C = C0;
    if (bx >= nblk) { B = B1; C = C1; bx -= nblk; }
    int n0 = bx * 64;
    int m0 = blockIdx.y * 128;

    int tid  = threadIdx.x;
    int wid  = tid >> 5, lane = tid & 31;
    int g    = lane >> 2, t = lane & 3;
    int wm   = wid >> 1, wn = wid & 1;          // warp grid 4x2
    int wr   = wm * 32;
    int wc   = wn * 32;

    float acc[2][4][4];
#pragma unroll
    for (int i = 0; i < 2; i++)
#pragma unroll
        for (int j = 0; j < 4; j++)
#pragma unroll
            for (int q = 0; q < 4; q++) acc[i][j][q] = 0.f;

    int arow = tid >> 3;           // 0..31 per pass
    int ac4  = tid & 7;            // float4 col
    int bn   = tid & 63;           // B col
    int bk0  = tid >> 6;           // 0..3

    for (int k0 = 0; k0 < K; k0 += BKG) {
        // A tile: 128 x 32, convert to tf32 bits
#pragma unroll
        for (int p = 0; p < 4; p++) {
            int r = p * 32 + arow;
            int gr = m0 + r; if (gr >= M) gr = M - 1;
            float4 v = *(const float4*)(A + (size_t)gr * K + k0 + ac4 * 4);
            uint4 u = make_uint4(f2tf32(v.x), f2tf32(v.y), f2tf32(v.z), f2tf32(v.w));
            *(uint4*)&As[r][ac4 * 4] = u;
        }
        // B tile: 32 x 64 from [K,N], stored transposed Bs[n][k]
#pragma unroll
        for (int j = 0; j < 8; j++) {
            int k = bk0 + j * 4;
            float v = B[(size_t)(k0 + k) * Nn + n0 + bn];
            Bs[bn][k] = f2tf32(v);
        }
        __syncthreads();

#pragma unroll
        for (int ks = 0; ks < BKG / 8; ks++) {
            int kk = ks * 8;
            uint32_t af[2][4], bf[4][2];
#pragma unroll
            for (int mt = 0; mt < 2; mt++) {
                int r = wr + mt * 16 + g;
                af[mt][0] = As[r][kk + t];
                af[mt][1] = As[r + 8][kk + t];
                af[mt][2] = As[r][kk + t + 4];
                af[mt][3] = As[r + 8][kk + t + 4];
            }
#pragma unroll
            for (int nt = 0; nt < 4; nt++) {
                int n = wc + nt * 8 + g;
                bf[nt][0] = Bs[n][kk + t];
                bf[nt][1] = Bs[n][kk + t + 4];
            }
#pragma unroll
            for (int mt = 0; mt < 2; mt++)
#pragma unroll
                for (int nt = 0; nt < 4; nt++)
                    mma_m16n8k8(acc[mt][nt], af[mt], bf[nt]);
        }
        __syncthreads();
    }

    // epilogue
#pragma unroll
    for (int mt = 0; mt < 2; mt++) {
        int r0 = m0 + wr + mt * 16 + g;
        int r1 = r0 + 8;
#pragma unroll
        for (int nt = 0; nt < 4; nt++) {
            int cc = n0 + wc + nt * 8 + t * 2;
            if (r0 < M)
                *(float2*)(C + (size_t)r0 * Nn + cc) = make_float2(acc[mt][nt][0], acc[mt][nt][1]);
            if (r1 < M)
                *(float2*)(C + (size_t)r1 * Nn + cc) = make_float2(acc[mt][nt][2], acc[mt][nt][3]);
        }
    }
}

// ---------------- CSR build ----------------
__global__ void k_init_deg(int n) {
    int i = blockIdx.x * blockDim.x + threadIdx.x;
    if (i < n) g_deg[i] = 1;   // self loop
}

__global__ void k_hist(const int* __restrict__ ei, int E) {
    int e = blockIdx.x * blockDim.x + threadIdx.x;
    if (e < E) atomicAdd(&g_deg[ei[E + e]], 1);
}

// 1024-thread shuffle-based exclusive scan
__global__ void k_scan(int n) {
    __shared__ int wsum[32];
    __shared__ int carry;
    int tid = threadIdx.x, lane = tid & 31, wid = tid >> 5;
    if (tid == 0) carry = 0;
    __syncthreads();
    for (int base = 0; base < n; base += 1024) {
        int i = base + tid;
        int v = (i < n) ? g_deg[i] : 0;
        int incl = v;
#pragma unroll
        for (int off = 1; off < 32; off <<= 1) {
            int tt = __shfl_up_sync(0xffffffffu, incl, off);
            if (lane >= off) incl += tt;
        }
        if (lane == 31) wsum[wid] = incl;
        __syncthreads();
        if (wid == 0) {
            int s = wsum[lane];
#pragma unroll
            for (int off = 1; off < 32; off <<= 1) {
                int tt = __shfl_up_sync(0xffffffffu, s, off);
                if (lane >= off) s += tt;
            }
            wsum[lane] = s;
        }
        __syncthreads();
        int woff = wid ? wsum[wid - 1] : 0;
        int c = carry;
        if (i < n) g_row[i] = c + woff + incl - v;
        __syncthreads();
        if (tid == 0) carry = c + wsum[31];
        __syncthreads();
    }
    if (tid == 0) g_row[n] = carry;
}

__global__ void k_csr_init(int n) {
    int i = blockIdx.x * blockDim.x + threadIdx.x;
    if (i < n) {
        int r = g_row[i];
        g_csr[r] = i;
        g_cur[i] = r + 1;
    }
}

__global__ void k_scatter(const int* __restrict__ ei, int E) {
    int e = blockIdx.x * blockDim.x + threadIdx.x;
    if (e < E) {
        int dst = ei[E + e];
        int pos = atomicAdd(&g_cur[dst], 1);
        g_csr[pos] = ei[e];
    }
}

// ---------------- GATv2 aggregation, layer 1 ----------------
__global__ void k_agg1(const float* __restrict__ att, const float* __restrict__ bias) {
    int warp = (blockIdx.x * blockDim.x + threadIdx.x) >> 5;
    if (warp >= NN) return;
    int lane = threadIdx.x & 31;
    int base = (lane >> 2) * 32 + (lane & 3) * 8;

    float xr[8], av[8];
    {
        float4 r0 = *(const float4*)(g_xr1 + (size_t)warp * F1 + base);
        float4 r1 = *(const float4*)(g_xr1 + (size_t)warp * F1 + base + 4);
        xr[0]=r0.x; xr[1]=r0.y; xr[2]=r0.z; xr[3]=r0.w;
        xr[4]=r1.x; xr[5]=r1.y; xr[6]=r1.z; xr[7]=r1.w;
        float4 a0 = *(const float4*)(att + base);
        float4 a1 = *(const float4*)(att + base + 4);
        av[0]=a0.x; av[1]=a0.y; av[2]=a0.z; av[3]=a0.w;
        av[4]=a1.x; av[5]=a1.y; av[6]=a1.z; av[7]=a1.w;
    }

    float acc[8];
#pragma unroll
    for (int j = 0; j < 8; j++) acc[j] = 0.f;
    float m = -3.0e38f, z = 0.f;

    int e0 = g_row[warp], e1 = g_row[warp + 1];
    float4 nx0, nx1;
    {
        int src = g_csr[e0];
        const float* xp = g_xl1 + (size_t)src * F1 + base;
        nx0 = *(const float4*)xp;
        nx1 = *(const float4*)(xp + 4);
    }
    for (int e = e0; e < e1; e++) {
        float4 x0 = nx0, x1 = nx1;
        if (e + 1 < e1) {
            int s2 = g_csr[e + 1];
            const float* xp = g_xl1 + (size_t)s2 * F1 + base;
            nx0 = *(const float4*)xp;
            nx1 = *(const float4*)(xp + 4);
        }
        float xj[8] = {x0.x, x0.y, x0.z, x0.w, x1.x, x1.y, x1.z, x1.w};
        float t = 0.f;
#pragma unroll
        for (int j = 0; j < 8; j++) {
            float v = xj[j] + xr[j];
            v = (v > 0.f) ? v : 0.2f * v;
            t = fmaf(v, av[j], t);
        }
        t += __shfl_xor_sync(0xffffffffu, t, 1);
        t += __shfl_xor_sync(0xffffffffu, t, 2);
        float mn = fmaxf(m, t);
        float sc = __expf(m - mn);
        float w  = __expf(t - mn);
        z = z * sc + w;
#pragma unroll
        for (int j = 0; j < 8; j++)
            acc[j] = fmaf(acc[j], sc, w * xj[j]);
        m = mn;
    }
    float inv = 1.f / z;
    float* out = g_h1 + (size_t)warp * F1 + base;
#pragma unroll
    for (int j = 0; j < 8; j++) {
        float v = acc[j] * inv + bias[base + j];
        out[j] = (v > 0.f) ? v : expm1f(v);        // ELU fused
    }
}

// ---------------- GATv2 aggregation, layer 2 ----------------
__global__ void k_agg2(const float* __restrict__ att, const float* __restrict__ bias) {
    int warp = (blockIdx.x * blockDim.x + threadIdx.x) >> 5;
    if (warp >= NN) return;
    int lane = threadIdx.x & 31;
    int base = (lane >> 4) * 32 + (lane & 15) * 2;

    float2 xr = *(const float2*)(g_xr2 + (size_t)warp * F2 + base);
    float2 av = *(const float2*)(att + base);

    float acc0 = 0.f, acc1 = 0.f;
    float m = -3.0e38f, z = 0.f;

    int e0 = g_row[warp], e1 = g_row[warp + 1];
    float2 nx = *(const float2*)(g_xl2 + (size_t)g_csr[e0] * F2 + base);
    for (int e = e0; e < e1; e++) {
        float2 xj = nx;
        if (e + 1 < e1)
            nx = *(const float2*)(g_xl2 + (size_t)g_csr[e + 1] * F2 + base);
        float v0 = xj.x + xr.x; v0 = (v0 > 0.f) ? v0 : 0.2f * v0;
        float v1 = xj.y + xr.y; v1 = (v1 > 0.f) ? v1 : 0.2f * v1;
        float t = fmaf(v0, av.x, v1 * av.y);
        t += __shfl_xor_sync(0xffffffffu, t, 1);
        t += __shfl_xor_sync(0xffffffffu, t, 2);
        t += __shfl_xor_sync(0xffffffffu, t, 4);
        t += __shfl_xor_sync(0xffffffffu, t, 8);
        float mn = fmaxf(m, t);
        float sc = __expf(m - mn);
        float w  = __expf(t - mn);
        z = z * sc + w;
        acc0 = fmaf(acc0, sc, w * xj.x);
        acc1 = fmaf(acc1, sc, w * xj.y);
        m = mn;
    }
    float inv = 1.f / z;
    g_h2[(size_t)warp * F2 + base + 0] = acc0 * inv + bias[base + 0];
    g_h2[(size_t)warp * F2 + base + 1] = acc1 * inv + bias[base + 1];
}

// ---------------- mean pool over sorted batch ----------------
__device__ __forceinline__ int lb(const int* b, int n, int g) {
    int lo = 0, hi = n;
    while (lo < hi) { int mid = (lo + hi) >> 1; if (b[mid] < g) lo = mid + 1; else hi = mid; }
    return lo;
}

__global__ void k_pool(const int* __restrict__ batch, int n) {
    __shared__ float part[4][64];
    int g = blockIdx.x;            // 64 blocks x 256 threads
    int d = threadIdx.x & 63;
    int ty = threadIdx.x >> 6;     // 0..3
    int s = lb(batch, n, g);
    int e = lb(batch, n, g + 1);
    float sum = 0.f;
    for (int i = s + ty; i < e; i += 4) sum += g_h2[(size_t)i * F2 + d];
    part[ty][d] = sum;
    __syncthreads();
    if (ty == 0) {
        float tot = part[0][d] + part[1][d] + part[2][d] + part[3][d];
        int cnt = e - s; if (cnt < 1) cnt = 1;
        g_pool[g * F2 + d] = tot / (float)cnt;
    }
}

// ---------------- MLP head ----------------
__global__ void k_mlp(const float* __restrict__ fc1w, const float* __restrict__ fc1b,
                      const float* __restrict__ fc2w, const float* __restrict__ fc2b,
                      const float* __restrict__ fcw,  const float* __restrict__ fcb,
                      float* __restrict__ out) {
    __shared__ float hg[GG * 64];
    __shared__ float x1[GG * 32];
    __shared__ float x2[GG * 16];
    int tid = threadIdx.x;
    for (int i = tid; i < GG * 64; i += 256) hg[i] = g_pool[i];
    __syncthreads();
    for (int i = tid; i < GG * 32; i += 256) {
        int g = i >> 5, o = i & 31;
        float s = fc1b[o];
        for (int k = 0; k < 64; k++) s = fmaf(hg[g * 64 + k], fc1w[k * 32 + o], s);
        x1[i] = fmaxf(s, 0.f);
    }
    __syncthreads();
    for (int i = tid; i < GG * 16; i += 256) {
        int g = i >> 4, o = i & 15;
        float s = fc2b[o];
        for (int k = 0; k < 32; k++) s = fmaf(x1[g * 32 + k], fc2w[k * 16 + o], s);
        float v = fmaxf(s, 0.f);
        x2[i] = v;
        out[GG * DOUT + i] = v;
    }
    __syncthreads();
    for (int i = tid; i < GG * DOUT; i += 256) {
        int g = i / DOUT, o = i - g * DOUT;
        float s = fcb[o];
        for (int k = 0; k < 16; k++) s = fmaf(x2[g * 16 + k], fcw[k * DOUT + o], s);
        out[i] = s;
    }
}

// ---------------- launch ----------------
extern "C" void kernel_launch(void* const* d_in, const int* in_sizes, int n_in,
                              void* d_out, int out_size) {
    const float* x    = (const float*)d_in[0];
    const int*   ei   = (const int*)  d_in[1];
    const int*   bat  = (const int*)  d_in[2];
    const float* W1l  = (const float*)d_in[3];
    const float* W1r  = (const float*)d_in[4];
    const float* a1   = (const float*)d_in[5];
    const float* b1   = (const float*)d_in[6];
    const float* W2l  = (const float*)d_in[7];
    const float* W2r  = (const float*)d_in[8];
    const float* a2   = (const float*)d_in[9];
    const float* b2   = (const float*)d_in[10];
    const float* fc1w = (const float*)d_in[11];
    const float* fc1b = (const float*)d_in[12];
    const float* fc2w = (const float*)d_in[13];
    const float* fc2b = (const float*)d_in[14];
    const float* fcw  = (const float*)d_in[15];
    const float* fcb  = (const float*)d_in[16];
    float* out = (float*)d_out;

    int E = in_sizes[1] / 2;

    float *xl1, *xr1, *h1, *xl2, *xr2;
    cudaGetSymbolAddress((void**)&xl1, g_xl1);
    cudaGetSymbolAddress((void**)&xr1, g_xr1);
    cudaGetSymbolAddress((void**)&h1,  g_h1);
    cudaGetSymbolAddress((void**)&xl2, g_xl2);
    cudaGetSymbolAddress((void**)&xr2, g_xr2);

    const int GRID_M = (NN + 127) / 128;   // 235

    // CSR front half (independent of GEMM)
    k_init_deg<<<(NN + 255) / 256, 256>>>(NN);            // launch 0
    k_hist<<<(E + 255) / 256, 256>>>(ei, E);              // launch 1
    k_scan<<<1, 1024>>>(NN);                              // launch 2

    // layer 1 linear transforms, merged l+r  (launch 3 -> ncu capture window)
    k_mma_gemm2<<<dim3(2 * F1 / 64, GRID_M), 256>>>(x, W1l, W1r, xl1, xr1,
                                                    NN, DIN, F1);

    // CSR back half
    k_csr_init<<<(NN + 255) / 256, 256>>>(NN);            // launch 4
    k_scatter<<<(E + 255) / 256, 256>>>(ei, E);           // launch 5

    // layer 1 attention + aggregation (+ELU fused)
    k_agg1<<<(NN * 32 + 255) / 256, 256>>>(a1, b1);       // launch 6

    // layer 2 linear transforms, merged l+r
    k_mma_gemm2<<<dim3(2 * F2 / 64, GRID_M), 256>>>(h1, W2l, W2r, xl2, xr2,
                                                    NN, F1, F2);

    // layer 2 attention + aggregation (+bias)
    k_agg2<<<(NN * 32 + 255) / 256, 256>>>(a2, b2);

    // pool + MLP head
    k_pool<<<GG, 256>>>(bat, NN);
    k_mlp<<<1, 256>>>(fc1w, fc1b, fc2w, fc2b, fcw, fcb, out);
}